// round 10
// baseline (speedup 1.0000x reference)
#include <cuda_runtime.h>
#include <cuda_fp16.h>
#include <math.h>

#define NN   1024
#define HH   128
#define DD   256
#define NLVL 3
#define LN_EPS 1e-5f

// -------- device scratch (static: allocation-free kernel_launch) --------
__device__ float g_x[NN*HH];
__device__ float g_pre[NN*HH];
__device__ float g_prj[NN*HH];
__device__ float g_msum[NN*HH];
__device__ float g_esum[NN*HH];     // sum_j ew[i,j,h]  (level-invariant)
__device__ float g_lmean[NLVL*HH];
__device__ __half g_ew[(long long)NN*NN*HH];  // 256 MB fp16, level-invariant

// 1-MUFU silu: silu(x) = 0.5*x*(1 + tanh(0.5*x))
__device__ __forceinline__ float silu_f(float x) {
    float t;
    asm("tanh.approx.f32 %0, %1;" : "=f"(t) : "f"(x * 0.5f));
    float hx = 0.5f * x;
    return fmaf(hx, t, hx);
}

__device__ __forceinline__ float warp_sum(float v) {
    #pragma unroll
    for (int off = 16; off; off >>= 1)
        v += __shfl_xor_sync(0xffffffffu, v, off);
    return v;
}

// ---------------------------------------------------------------
__global__ void k_init(const int* __restrict__ an, const float* __restrict__ emb) {
    int t = blockIdx.x * blockDim.x + threadIdx.x;
    if (t < NLVL*HH) g_lmean[t] = 0.f;
    int n = t >> 7;
    int h = t & 127;
    g_x[t] = emb[an[n]*HH + h];
}

// ---------------------------------------------------------------
// ew[i,j,:] = LN(silu(scales(i,j) @ de_W + de_b)) * de_g + de_be   (fp16 out)
// Repartitioned: 16 lanes per (i,j), 8 h/lane, 2 pairs per warp.
// Symmetric: compute j>=i, write both mirrors (stores predicated;
// compute is unconditional so all 32 lanes join the shuffles).
// grid (64, 1024), block 256 -> 16 j per block.
__global__ void __launch_bounds__(256) k_ew(
    const float* __restrict__ pos,
    const float* __restrict__ deW, const float* __restrict__ deb,
    const float* __restrict__ deg, const float* __restrict__ debe)
{
    int warp = threadIdx.x >> 5;
    int lane = threadIdx.x & 31;
    int grp  = lane >> 4;
    int l16  = lane & 15;
    int i     = blockIdx.y;
    int jbase = blockIdx.x << 4;
    if (jbase + 15 < i) return;          // block fully below diagonal
    int j = jbase + (warp << 1) + grp;

    float dx = pos[3*i]   - pos[3*j];
    float dy = pos[3*i+1] - pos[3*j+1];
    float dz = pos[3*i+2] - pos[3*j+2];
    float sq = dx*dx + dy*dy + dz*dz;
    float d  = (sq > 0.f) ? sqrtf(sq) : 0.f;
    float s3 = __expf(-0.25f * d);
    float s2 = s3 * s3;
    float s1 = s2 * s2;

    int h0 = l16 << 3;                   // 8 h per lane
    float v[8];
    #pragma unroll
    for (int half = 0; half < 2; half++) {
        int hh = h0 + half*4;
        float4 w0 = *(const float4*)(deW + hh);
        float4 w1 = *(const float4*)(deW + HH + hh);
        float4 w2 = *(const float4*)(deW + 2*HH + hh);
        float4 bb = *(const float4*)(deb + hh);
        v[half*4+0] = fmaf(s1, w0.x, fmaf(s2, w1.x, fmaf(s3, w2.x, bb.x)));
        v[half*4+1] = fmaf(s1, w0.y, fmaf(s2, w1.y, fmaf(s3, w2.y, bb.y)));
        v[half*4+2] = fmaf(s1, w0.z, fmaf(s2, w1.z, fmaf(s3, w2.z, bb.z)));
        v[half*4+3] = fmaf(s1, w0.w, fmaf(s2, w1.w, fmaf(s3, w2.w, bb.w)));
    }
    #pragma unroll
    for (int k = 0; k < 8; k++) v[k] = silu_f(v[k]);

    float p = ((v[0]+v[1])+(v[2]+v[3])) + ((v[4]+v[5])+(v[6]+v[7]));
    float q = fmaf(v[0],v[0], fmaf(v[1],v[1], fmaf(v[2],v[2], v[3]*v[3])))
            + fmaf(v[4],v[4], fmaf(v[5],v[5], fmaf(v[6],v[6], v[7]*v[7])));
    #pragma unroll
    for (int off = 8; off; off >>= 1) {
        p += __shfl_xor_sync(0xffffffffu, p, off);
        q += __shfl_xor_sync(0xffffffffu, q, off);
    }
    float mu   = p * (1.f/HH);
    float var  = fmaf(-mu, mu, q * (1.f/HH));
    float rstd = rsqrtf(var + LN_EPS);

    __half2 oh[4];
    #pragma unroll
    for (int half = 0; half < 2; half++) {
        int hh = h0 + half*4;
        float4 gg = *(const float4*)(deg + hh);
        float4 be = *(const float4*)(debe + hh);
        float o0 = fmaf((v[half*4+0] - mu) * rstd, gg.x, be.x);
        float o1 = fmaf((v[half*4+1] - mu) * rstd, gg.y, be.y);
        float o2 = fmaf((v[half*4+2] - mu) * rstd, gg.z, be.z);
        float o3 = fmaf((v[half*4+3] - mu) * rstd, gg.w, be.w);
        oh[half*2+0] = __floats2half2_rn(o0, o1);
        oh[half*2+1] = __floats2half2_rn(o2, o3);
    }
    uint4 pack;
    pack.x = *(unsigned*)&oh[0]; pack.y = *(unsigned*)&oh[1];
    pack.z = *(unsigned*)&oh[2]; pack.w = *(unsigned*)&oh[3];

    if (j >= i) {
        __stcs((uint4*)(g_ew + ((long long)i*NN + j)*HH + h0), pack);
        if (j != i)
            __stcs((uint4*)(g_ew + ((long long)j*NN + i)*HH + h0), pack);
    }
}

// ---------------------------------------------------------------
// pre = x@Wi + msg_b, prj = x@Wj.  8 nodes/block, 128 threads (h).
__global__ void __launch_bounds__(128) k_preprj(
    const float* __restrict__ msgW, const float* __restrict__ msgb, int lvl)
{
    __shared__ float xs[8][HH];
    int h  = threadIdx.x;
    int n0 = blockIdx.x << 3;
    #pragma unroll
    for (int nn = 0; nn < 8; nn++) xs[nn][h] = g_x[(n0+nn)*HH + h];
    __syncthreads();

    const float* Wi = msgW + (size_t)lvl*2*HH*HH;
    const float* Wj = Wi + HH*HH;
    float ai[8], aj[8];
    #pragma unroll
    for (int nn = 0; nn < 8; nn++) { ai[nn] = 0.f; aj[nn] = 0.f; }

    for (int k = 0; k < HH; k++) {
        float wi = Wi[k*HH + h];
        float wj = Wj[k*HH + h];
        #pragma unroll
        for (int nn = 0; nn < 8; nn++) {
            ai[nn] = fmaf(xs[nn][k], wi, ai[nn]);
            aj[nn] = fmaf(xs[nn][k], wj, aj[nn]);
        }
    }
    float bb = msgb[lvl*HH + h];
    #pragma unroll
    for (int nn = 0; nn < 8; nn++) {
        g_pre[(n0+nn)*HH + h] = ai[nn] + bb;
        g_prj[(n0+nn)*HH + h] = aj[nn];
    }
}

// ---------------------------------------------------------------
// msum[i,h] = g[h]*sum_j (s-mu)*rstd*e  +  be[h]*sum_j e
// 16 lanes per j (8 h each), 2 j per warp; 4-step group butterfly.
template<bool FIRST>
__global__ void __launch_bounds__(256) k_msum(
    const float* __restrict__ msgg, const float* __restrict__ msgbe, int lvl)
{
    __shared__ float red[16][HH];
    __shared__ float red2[16][HH];   // only used when FIRST
    int i    = blockIdx.x;
    int warp = threadIdx.x >> 5;
    int lane = threadIdx.x & 31;
    int grp  = lane >> 4;
    int l16  = lane & 15;
    int h0   = l16 << 3;

    float pre[8];
    *(float4*)(pre)     = *(const float4*)(g_pre + i*HH + h0);
    *(float4*)(pre + 4) = *(const float4*)(g_pre + i*HH + h0 + 4);

    float a[8] = {0,0,0,0,0,0,0,0};
    float z[8] = {0,0,0,0,0,0,0,0};

    const __half* ewbase = g_ew + (long long)i*NN*HH + h0;
    int jfix = (warp << 1) + grp;

    #pragma unroll 2
    for (int jj = 0; jj < NN/16; jj++) {
        int j = (jj << 4) + jfix;
        float4 pja = *(const float4*)(g_prj + j*HH + h0);
        float4 pjb = *(const float4*)(g_prj + j*HH + h0 + 4);
        uint4  epk = __ldcs((const uint4*)(ewbase + (long long)j*HH));

        float s[8];
        s[0] = silu_f(pre[0] + pja.x);
        s[1] = silu_f(pre[1] + pja.y);
        s[2] = silu_f(pre[2] + pja.z);
        s[3] = silu_f(pre[3] + pja.w);
        s[4] = silu_f(pre[4] + pjb.x);
        s[5] = silu_f(pre[5] + pjb.y);
        s[6] = silu_f(pre[6] + pjb.z);
        s[7] = silu_f(pre[7] + pjb.w);

        float p = ((s[0]+s[1])+(s[2]+s[3])) + ((s[4]+s[5])+(s[6]+s[7]));
        float q = fmaf(s[0],s[0], fmaf(s[1],s[1], fmaf(s[2],s[2], s[3]*s[3])))
                + fmaf(s[4],s[4], fmaf(s[5],s[5], fmaf(s[6],s[6], s[7]*s[7])));
        #pragma unroll
        for (int off = 8; off; off >>= 1) {
            p += __shfl_xor_sync(0xffffffffu, p, off);
            q += __shfl_xor_sync(0xffffffffu, q, off);
        }
        float mu   = p * (1.f/HH);
        float var  = fmaf(-mu, mu, q * (1.f/HH));
        float rstd = rsqrtf(var + LN_EPS);
        float c0   = -mu * rstd;

        unsigned u0 = epk.x, u1 = epk.y, u2 = epk.z, u3 = epk.w;
        float2 f0 = __half22float2(*(__half2*)&u0);
        float2 f1 = __half22float2(*(__half2*)&u1);
        float2 f2 = __half22float2(*(__half2*)&u2);
        float2 f3 = __half22float2(*(__half2*)&u3);
        float e[8] = { f0.x, f0.y, f1.x, f1.y, f2.x, f2.y, f3.x, f3.y };

        #pragma unroll
        for (int k = 0; k < 8; k++) {
            a[k] = fmaf(fmaf(s[k], rstd, c0), e[k], a[k]);
            if (FIRST) z[k] += e[k];
        }
    }

    int slot = (warp << 1) | grp;
    #pragma unroll
    for (int k = 0; k < 8; k++) red[slot][h0+k] = a[k];
    if (FIRST) {
        #pragma unroll
        for (int k = 0; k < 8; k++) red2[slot][h0+k] = z[k];
    }
    __syncthreads();
    if (threadIdx.x < HH) {
        int h = threadIdx.x;
        float S1 = 0.f, S0 = 0.f;
        #pragma unroll
        for (int w = 0; w < 16; w++) S1 += red[w][h];
        if (FIRST) {
            #pragma unroll
            for (int w = 0; w < 16; w++) S0 += red2[w][h];
            g_esum[i*HH + h] = S0;
        } else {
            S0 = g_esum[i*HH + h];
        }
        g_msum[i*HH + h] = fmaf(msgg[lvl*HH + h], S1, msgbe[lvl*HH + h] * S0);
    }
}

// ---------------------------------------------------------------
// x += LN(silu([x, msum] @ upd_W + upd_b)); accumulate level mean.
__global__ void __launch_bounds__(128) k_upd(
    const float* __restrict__ updW, const float* __restrict__ updb,
    const float* __restrict__ updg, const float* __restrict__ updbe, int lvl)
{
    __shared__ float us[2*HH];
    __shared__ float rp[4], rq[4];
    __shared__ float s_mu, s_rstd;
    int i = blockIdx.x;
    int h = threadIdx.x;
    int warp = h >> 5, lane = h & 31;

    us[h]      = g_x[i*HH + h];
    us[HH + h] = g_msum[i*HH + h];
    __syncthreads();

    const float* W = updW + (size_t)lvl*2*HH*HH;
    float acc = updb[lvl*HH + h];
    #pragma unroll 4
    for (int k = 0; k < 2*HH; k++) acc = fmaf(us[k], W[k*HH + h], acc);

    float s = silu_f(acc);

    float p = warp_sum(s);
    float q = warp_sum(s*s);
    if (lane == 0) { rp[warp] = p; rq[warp] = q; }
    __syncthreads();
    if (h == 0) {
        float P = rp[0]+rp[1]+rp[2]+rp[3];
        float Q = rq[0]+rq[1]+rq[2]+rq[3];
        float mu = P * (1.f/HH);
        s_mu = mu;
        s_rstd = rsqrtf(fmaf(-mu, mu, Q * (1.f/HH)) + LN_EPS);
    }
    __syncthreads();

    float m  = fmaf((s - s_mu) * s_rstd, updg[lvl*HH + h], updbe[lvl*HH + h]);
    float xn = us[h] + m;
    g_x[i*HH + h] = xn;
    atomicAdd(&g_lmean[lvl*HH + h], xn * (1.f/NN));
}

// ---------------------------------------------------------------
__global__ void __launch_bounds__(256) k_final(
    const float* __restrict__ fpW, const float* __restrict__ fpb,
    const float* __restrict__ fpg, const float* __restrict__ fpbe,
    float* __restrict__ out)
{
    __shared__ float cs[NLVL*HH];
    __shared__ float rp[8], rq[8];
    __shared__ float s_mu, s_rstd;
    int t = threadIdx.x;
    int warp = t >> 5, lane = t & 31;

    for (int k = t; k < NLVL*HH; k += 256) cs[k] = g_lmean[k];
    __syncthreads();

    float acc = fpb[t];
    #pragma unroll 4
    for (int k = 0; k < NLVL*HH; k++) acc = fmaf(cs[k], fpW[k*DD + t], acc);

    float p = warp_sum(acc);
    float q = warp_sum(acc*acc);
    if (lane == 0) { rp[warp] = p; rq[warp] = q; }
    __syncthreads();
    if (t == 0) {
        float P = 0.f, Q = 0.f;
        #pragma unroll
        for (int w = 0; w < 8; w++) { P += rp[w]; Q += rq[w]; }
        float mu = P * (1.f/DD);
        s_mu = mu;
        s_rstd = rsqrtf(fmaf(-mu, mu, Q * (1.f/DD)) + LN_EPS);
    }
    __syncthreads();

    out[t] = fmaf((acc - s_mu) * s_rstd, fpg[t], fpbe[t]);
}

// ---------------------------------------------------------------
extern "C" void kernel_launch(void* const* d_in, const int* in_sizes, int n_in,
                              void* d_out, int out_size) {
    const int*   an    = (const int*)  d_in[0];
    const float* pos   = (const float*)d_in[1];
    const float* emb   = (const float*)d_in[2];
    const float* deW   = (const float*)d_in[3];
    const float* deb   = (const float*)d_in[4];
    const float* deg   = (const float*)d_in[5];
    const float* debe  = (const float*)d_in[6];
    const float* msgW  = (const float*)d_in[7];
    const float* msgb  = (const float*)d_in[8];
    const float* msgg  = (const float*)d_in[9];
    const float* msgbe = (const float*)d_in[10];
    const float* updW  = (const float*)d_in[11];
    const float* updb  = (const float*)d_in[12];
    const float* updg  = (const float*)d_in[13];
    const float* updbe = (const float*)d_in[14];
    const float* fpW   = (const float*)d_in[15];
    const float* fpb   = (const float*)d_in[16];
    const float* fpg   = (const float*)d_in[17];
    const float* fpbe  = (const float*)d_in[18];
    float* out = (float*)d_out;

    k_init<<<512, 256>>>(an, emb);
    k_ew<<<dim3(64, 1024), 256>>>(pos, deW, deb, deg, debe);
    for (int lvl = 0; lvl < NLVL; lvl++) {
        k_preprj<<<128, 128>>>(msgW, msgb, lvl);
        if (lvl == 0) k_msum<true><<<1024, 256>>>(msgg, msgbe, lvl);
        else          k_msum<false><<<1024, 256>>>(msgg, msgbe, lvl);
        k_upd<<<1024, 128>>>(updW, updb, updg, updbe, lvl);
    }
    k_final<<<1, 256>>>(fpW, fpb, fpg, fpbe, out);
}

// round 11
// speedup vs baseline: 1.0227x; 1.0227x over previous
#include <cuda_runtime.h>
#include <cuda_fp16.h>
#include <math.h>

#define NN   1024
#define HH   128
#define DD   256
#define NLVL 3
#define LN_EPS 1e-5f

// -------- device scratch (static: allocation-free kernel_launch) --------
__device__ float g_x[NN*HH];
__device__ float g_pre[NN*HH];
__device__ float g_prj[NN*HH];
__device__ float g_msum[NN*HH];
__device__ float g_esum[NN*HH];     // sum_j ew[i,j,h]  (level-invariant)
__device__ float g_lmean[NLVL*HH];
// Only the upper triangle (j >= i) is populated; ew is symmetric in (i,j).
__device__ __half g_ew[(long long)NN*NN*HH];

// 1-MUFU silu: silu(x) = 0.5*x*(1 + tanh(0.5*x))
__device__ __forceinline__ float silu_f(float x) {
    float t;
    asm("tanh.approx.f32 %0, %1;" : "=f"(t) : "f"(x * 0.5f));
    float hx = 0.5f * x;
    return fmaf(hx, t, hx);
}

__device__ __forceinline__ float warp_sum(float v) {
    #pragma unroll
    for (int off = 16; off; off >>= 1)
        v += __shfl_xor_sync(0xffffffffu, v, off);
    return v;
}

// ---------------------------------------------------------------
__global__ void k_init(const int* __restrict__ an, const float* __restrict__ emb) {
    int t = blockIdx.x * blockDim.x + threadIdx.x;
    if (t < NLVL*HH) g_lmean[t] = 0.f;
    int n = t >> 7;
    int h = t & 127;
    g_x[t] = emb[an[n]*HH + h];
}

// ---------------------------------------------------------------
// ew[i,j,:] = LN(silu(scales(i,j) @ de_W + de_b)) * de_g + de_be   (fp16 out)
// UPPER TRIANGLE ONLY (j >= i): one store per pair, no mirror.
// warp per (i,j); 4 h per lane. grid (128, 1024), block 256.
__global__ void __launch_bounds__(256) k_ew(
    const float* __restrict__ pos,
    const float* __restrict__ deW, const float* __restrict__ deb,
    const float* __restrict__ deg, const float* __restrict__ debe)
{
    int warp = threadIdx.x >> 5;
    int lane = threadIdx.x & 31;
    int i = blockIdx.y;
    int jbase = blockIdx.x << 3;
    if (jbase + 7 < i) return;           // block fully below diagonal
    int j = jbase + warp;
    if (j < i) return;                   // warp below diagonal

    float dx = pos[3*i]   - pos[3*j];
    float dy = pos[3*i+1] - pos[3*j+1];
    float dz = pos[3*i+2] - pos[3*j+2];
    float sq = dx*dx + dy*dy + dz*dz;
    float d  = (sq > 0.f) ? sqrtf(sq) : 0.f;
    float s3 = __expf(-0.25f * d);
    float s2 = s3 * s3;
    float s1 = s2 * s2;

    int h0 = lane << 2;
    float4 w0 = *(const float4*)(deW + h0);
    float4 w1 = *(const float4*)(deW + HH + h0);
    float4 w2 = *(const float4*)(deW + 2*HH + h0);
    float4 bb = *(const float4*)(deb + h0);

    float v0 = fmaf(s1, w0.x, fmaf(s2, w1.x, fmaf(s3, w2.x, bb.x)));
    float v1 = fmaf(s1, w0.y, fmaf(s2, w1.y, fmaf(s3, w2.y, bb.y)));
    float v2 = fmaf(s1, w0.z, fmaf(s2, w1.z, fmaf(s3, w2.z, bb.z)));
    float v3 = fmaf(s1, w0.w, fmaf(s2, w1.w, fmaf(s3, w2.w, bb.w)));

    v0 = silu_f(v0); v1 = silu_f(v1); v2 = silu_f(v2); v3 = silu_f(v3);

    float p = warp_sum(v0 + v1 + v2 + v3);
    float q = warp_sum(fmaf(v0,v0, fmaf(v1,v1, fmaf(v2,v2, v3*v3))));
    float mu   = p * (1.f/HH);
    float var  = fmaf(-mu, mu, q * (1.f/HH));
    float rstd = rsqrtf(var + LN_EPS);

    float4 gg = *(const float4*)(deg + h0);
    float4 be = *(const float4*)(debe + h0);
    float o0 = fmaf((v0 - mu) * rstd, gg.x, be.x);
    float o1 = fmaf((v1 - mu) * rstd, gg.y, be.y);
    float o2 = fmaf((v2 - mu) * rstd, gg.z, be.z);
    float o3 = fmaf((v3 - mu) * rstd, gg.w, be.w);

    __half2 ha = __floats2half2_rn(o0, o1);
    __half2 hb = __floats2half2_rn(o2, o3);
    float2 pack = make_float2(__uint_as_float(*(unsigned*)&ha),
                              __uint_as_float(*(unsigned*)&hb));
    __stcs((float2*)(g_ew + ((long long)i*NN + j)*HH + h0), pack);
}

// ---------------------------------------------------------------
// pre = x@Wi + msg_b, prj = x@Wj.  8 nodes/block, 128 threads (h).
__global__ void __launch_bounds__(128) k_preprj(
    const float* __restrict__ msgW, const float* __restrict__ msgb, int lvl)
{
    __shared__ float xs[8][HH];
    int h  = threadIdx.x;
    int n0 = blockIdx.x << 3;
    #pragma unroll
    for (int nn = 0; nn < 8; nn++) xs[nn][h] = g_x[(n0+nn)*HH + h];
    __syncthreads();

    const float* Wi = msgW + (size_t)lvl*2*HH*HH;
    const float* Wj = Wi + HH*HH;
    float ai[8], aj[8];
    #pragma unroll
    for (int nn = 0; nn < 8; nn++) { ai[nn] = 0.f; aj[nn] = 0.f; }

    for (int k = 0; k < HH; k++) {
        float wi = Wi[k*HH + h];
        float wj = Wj[k*HH + h];
        #pragma unroll
        for (int nn = 0; nn < 8; nn++) {
            ai[nn] = fmaf(xs[nn][k], wi, ai[nn]);
            aj[nn] = fmaf(xs[nn][k], wj, aj[nn]);
        }
    }
    float bb = msgb[lvl*HH + h];
    #pragma unroll
    for (int nn = 0; nn < 8; nn++) {
        g_pre[(n0+nn)*HH + h] = ai[nn] + bb;
        g_prj[(n0+nn)*HH + h] = aj[nn];
    }
}

// ---------------------------------------------------------------
// msum[i,h] = g[h]*sum_j (s-mu)*rstd*e  +  be[h]*sum_j e
// 16 lanes per j (8 h each), 2 j per warp; 4-step group butterfly.
// ew read from its symmetric home: ew[min(i,j)][max(i,j)].
template<bool FIRST>
__global__ void __launch_bounds__(256) k_msum(
    const float* __restrict__ msgg, const float* __restrict__ msgbe, int lvl)
{
    __shared__ float red[16][HH];
    __shared__ float red2[16][HH];   // only used when FIRST
    int i    = blockIdx.x;
    int warp = threadIdx.x >> 5;
    int lane = threadIdx.x & 31;
    int grp  = lane >> 4;
    int l16  = lane & 15;
    int h0   = l16 << 3;

    float pre[8];
    *(float4*)(pre)     = *(const float4*)(g_pre + i*HH + h0);
    *(float4*)(pre + 4) = *(const float4*)(g_pre + i*HH + h0 + 4);

    float a[8] = {0,0,0,0,0,0,0,0};
    float z[8] = {0,0,0,0,0,0,0,0};

    int jfix = (warp << 1) + grp;

    #pragma unroll 2
    for (int jj = 0; jj < NN/16; jj++) {
        int j = (jj << 4) + jfix;
        float4 pja = *(const float4*)(g_prj + j*HH + h0);
        float4 pjb = *(const float4*)(g_prj + j*HH + h0 + 4);
        // symmetric home of the (i,j) tile
        int lo = j < i ? j : i;
        int hi = j < i ? i : j;
        uint4 epk = __ldcs((const uint4*)(g_ew + ((long long)lo*NN + hi)*HH + h0));

        float s[8];
        s[0] = silu_f(pre[0] + pja.x);
        s[1] = silu_f(pre[1] + pja.y);
        s[2] = silu_f(pre[2] + pja.z);
        s[3] = silu_f(pre[3] + pja.w);
        s[4] = silu_f(pre[4] + pjb.x);
        s[5] = silu_f(pre[5] + pjb.y);
        s[6] = silu_f(pre[6] + pjb.z);
        s[7] = silu_f(pre[7] + pjb.w);

        float p = ((s[0]+s[1])+(s[2]+s[3])) + ((s[4]+s[5])+(s[6]+s[7]));
        float q = fmaf(s[0],s[0], fmaf(s[1],s[1], fmaf(s[2],s[2], s[3]*s[3])))
                + fmaf(s[4],s[4], fmaf(s[5],s[5], fmaf(s[6],s[6], s[7]*s[7])));
        #pragma unroll
        for (int off = 8; off; off >>= 1) {
            p += __shfl_xor_sync(0xffffffffu, p, off);
            q += __shfl_xor_sync(0xffffffffu, q, off);
        }
        float mu   = p * (1.f/HH);
        float var  = fmaf(-mu, mu, q * (1.f/HH));
        float rstd = rsqrtf(var + LN_EPS);
        float c0   = -mu * rstd;

        unsigned u0 = epk.x, u1 = epk.y, u2 = epk.z, u3 = epk.w;
        float2 f0 = __half22float2(*(__half2*)&u0);
        float2 f1 = __half22float2(*(__half2*)&u1);
        float2 f2 = __half22float2(*(__half2*)&u2);
        float2 f3 = __half22float2(*(__half2*)&u3);
        float e[8] = { f0.x, f0.y, f1.x, f1.y, f2.x, f2.y, f3.x, f3.y };

        #pragma unroll
        for (int k = 0; k < 8; k++) {
            a[k] = fmaf(fmaf(s[k], rstd, c0), e[k], a[k]);
            if (FIRST) z[k] += e[k];
        }
    }

    int slot = (warp << 1) | grp;
    #pragma unroll
    for (int k = 0; k < 8; k++) red[slot][h0+k] = a[k];
    if (FIRST) {
        #pragma unroll
        for (int k = 0; k < 8; k++) red2[slot][h0+k] = z[k];
    }
    __syncthreads();
    if (threadIdx.x < HH) {
        int h = threadIdx.x;
        float S1 = 0.f, S0 = 0.f;
        #pragma unroll
        for (int w = 0; w < 16; w++) S1 += red[w][h];
        if (FIRST) {
            #pragma unroll
            for (int w = 0; w < 16; w++) S0 += red2[w][h];
            g_esum[i*HH + h] = S0;
        } else {
            S0 = g_esum[i*HH + h];
        }
        g_msum[i*HH + h] = fmaf(msgg[lvl*HH + h], S1, msgbe[lvl*HH + h] * S0);
    }
}

// ---------------------------------------------------------------
// x += LN(silu([x, msum] @ upd_W + upd_b)); accumulate level mean.
__global__ void __launch_bounds__(128) k_upd(
    const float* __restrict__ updW, const float* __restrict__ updb,
    const float* __restrict__ updg, const float* __restrict__ updbe, int lvl)
{
    __shared__ float us[2*HH];
    __shared__ float rp[4], rq[4];
    __shared__ float s_mu, s_rstd;
    int i = blockIdx.x;
    int h = threadIdx.x;
    int warp = h >> 5, lane = h & 31;

    us[h]      = g_x[i*HH + h];
    us[HH + h] = g_msum[i*HH + h];
    __syncthreads();

    const float* W = updW + (size_t)lvl*2*HH*HH;
    float acc = updb[lvl*HH + h];
    #pragma unroll 4
    for (int k = 0; k < 2*HH; k++) acc = fmaf(us[k], W[k*HH + h], acc);

    float s = silu_f(acc);

    float p = warp_sum(s);
    float q = warp_sum(s*s);
    if (lane == 0) { rp[warp] = p; rq[warp] = q; }
    __syncthreads();
    if (h == 0) {
        float P = rp[0]+rp[1]+rp[2]+rp[3];
        float Q = rq[0]+rq[1]+rq[2]+rq[3];
        float mu = P * (1.f/HH);
        s_mu = mu;
        s_rstd = rsqrtf(fmaf(-mu, mu, Q * (1.f/HH)) + LN_EPS);
    }
    __syncthreads();

    float m  = fmaf((s - s_mu) * s_rstd, updg[lvl*HH + h], updbe[lvl*HH + h]);
    float xn = us[h] + m;
    g_x[i*HH + h] = xn;
    atomicAdd(&g_lmean[lvl*HH + h], xn * (1.f/NN));
}

// ---------------------------------------------------------------
__global__ void __launch_bounds__(256) k_final(
    const float* __restrict__ fpW, const float* __restrict__ fpb,
    const float* __restrict__ fpg, const float* __restrict__ fpbe,
    float* __restrict__ out)
{
    __shared__ float cs[NLVL*HH];
    __shared__ float rp[8], rq[8];
    __shared__ float s_mu, s_rstd;
    int t = threadIdx.x;
    int warp = t >> 5, lane = t & 31;

    for (int k = t; k < NLVL*HH; k += 256) cs[k] = g_lmean[k];
    __syncthreads();

    float acc = fpb[t];
    #pragma unroll 4
    for (int k = 0; k < NLVL*HH; k++) acc = fmaf(cs[k], fpW[k*DD + t], acc);

    float p = warp_sum(acc);
    float q = warp_sum(acc*acc);
    if (lane == 0) { rp[warp] = p; rq[warp] = q; }
    __syncthreads();
    if (t == 0) {
        float P = 0.f, Q = 0.f;
        #pragma unroll
        for (int w = 0; w < 8; w++) { P += rp[w]; Q += rq[w]; }
        float mu = P * (1.f/DD);
        s_mu = mu;
        s_rstd = rsqrtf(fmaf(-mu, mu, Q * (1.f/DD)) + LN_EPS);
    }
    __syncthreads();

    out[t] = fmaf((acc - s_mu) * s_rstd, fpg[t], fpbe[t]);
}

// ---------------------------------------------------------------
extern "C" void kernel_launch(void* const* d_in, const int* in_sizes, int n_in,
                              void* d_out, int out_size) {
    const int*   an    = (const int*)  d_in[0];
    const float* pos   = (const float*)d_in[1];
    const float* emb   = (const float*)d_in[2];
    const float* deW   = (const float*)d_in[3];
    const float* deb   = (const float*)d_in[4];
    const float* deg   = (const float*)d_in[5];
    const float* debe  = (const float*)d_in[6];
    const float* msgW  = (const float*)d_in[7];
    const float* msgb  = (const float*)d_in[8];
    const float* msgg  = (const float*)d_in[9];
    const float* msgbe = (const float*)d_in[10];
    const float* updW  = (const float*)d_in[11];
    const float* updb  = (const float*)d_in[12];
    const float* updg  = (const float*)d_in[13];
    const float* updbe = (const float*)d_in[14];
    const float* fpW   = (const float*)d_in[15];
    const float* fpb   = (const float*)d_in[16];
    const float* fpg   = (const float*)d_in[17];
    const float* fpbe  = (const float*)d_in[18];
    float* out = (float*)d_out;

    k_init<<<512, 256>>>(an, emb);
    k_ew<<<dim3(128, 1024), 256>>>(pos, deW, deb, deg, debe);
    for (int lvl = 0; lvl < NLVL; lvl++) {
        k_preprj<<<128, 128>>>(msgW, msgb, lvl);
        if (lvl == 0) k_msum<true><<<1024, 256>>>(msgg, msgbe, lvl);
        else          k_msum<false><<<1024, 256>>>(msgg, msgbe, lvl);
        k_upd<<<1024, 128>>>(updW, updb, updg, updbe, lvl);
    }
    k_final<<<1, 256>>>(fpW, fpb, fpg, fpbe, out);
}

// round 12
// speedup vs baseline: 1.1040x; 1.0795x over previous
#include <cuda_runtime.h>
#include <cuda_fp16.h>
#include <math.h>

#define NN   1024
#define HH   128
#define DD   256
#define NLVL 3
#define LN_EPS 1e-5f

// -------- device scratch (static: allocation-free kernel_launch) --------
__device__ float g_x[NN*HH];
__device__ float g_pre[NN*HH];
__device__ float g_prj[NN*HH];
__device__ float g_msum[NN*HH];
__device__ float g_esum[NN*HH];     // sum_j ew[i,j,h]  (level-invariant)
__device__ float g_lmean[NLVL*HH];
__device__ __half g_ew[(long long)NN*NN*HH];  // 256 MB fp16, full matrix (mirrored)

// 1-MUFU silu: silu(x) = 0.5*x*(1 + tanh(0.5*x))
__device__ __forceinline__ float silu_f(float x) {
    float t;
    asm("tanh.approx.f32 %0, %1;" : "=f"(t) : "f"(x * 0.5f));
    float hx = 0.5f * x;
    return fmaf(hx, t, hx);
}

__device__ __forceinline__ float warp_sum(float v) {
    #pragma unroll
    for (int off = 16; off; off >>= 1)
        v += __shfl_xor_sync(0xffffffffu, v, off);
    return v;
}

// ---------------------------------------------------------------
__global__ void k_init(const int* __restrict__ an, const float* __restrict__ emb) {
    int t = blockIdx.x * blockDim.x + threadIdx.x;
    if (t < NLVL*HH) g_lmean[t] = 0.f;
    int n = t >> 7;
    int h = t & 127;
    g_x[t] = emb[an[n]*HH + h];
}

// ---------------------------------------------------------------
// ew[i,j,:] = LN(silu(scales(i,j) @ de_W + de_b)) * de_g + de_be  (fp16)
// Persistent loop form: 512 blocks; block b covers upper-triangle rows
// {b, 1023-b} (constant 1025 pairs). Weights cached in registers once.
// 16 lanes per pair (8 h each), 2 pairs per warp; mirror stores.
__global__ void __launch_bounds__(256) k_ew(
    const float* __restrict__ pos,
    const float* __restrict__ deW, const float* __restrict__ deb,
    const float* __restrict__ deg, const float* __restrict__ debe)
{
    int warp = threadIdx.x >> 5;
    int lane = threadIdx.x & 31;
    int grp  = lane >> 4;
    int l16  = lane & 15;
    int h0   = l16 << 3;                 // 8 h per lane
    int jfix = (warp << 1) + grp;        // 0..15

    // per-block weight cache (registers)
    float w0[8], w1[8], w2[8], wb[8], wg[8], we[8];
    *(float4*)(w0)   = *(const float4*)(deW + h0);
    *(float4*)(w0+4) = *(const float4*)(deW + h0 + 4);
    *(float4*)(w1)   = *(const float4*)(deW + HH + h0);
    *(float4*)(w1+4) = *(const float4*)(deW + HH + h0 + 4);
    *(float4*)(w2)   = *(const float4*)(deW + 2*HH + h0);
    *(float4*)(w2+4) = *(const float4*)(deW + 2*HH + h0 + 4);
    *(float4*)(wb)   = *(const float4*)(deb + h0);
    *(float4*)(wb+4) = *(const float4*)(deb + h0 + 4);
    *(float4*)(wg)   = *(const float4*)(deg + h0);
    *(float4*)(wg+4) = *(const float4*)(deg + h0 + 4);
    *(float4*)(we)   = *(const float4*)(debe + h0);
    *(float4*)(we+4) = *(const float4*)(debe + h0 + 4);

    #pragma unroll
    for (int half = 0; half < 2; half++) {
        int i = half ? (NN - 1 - (int)blockIdx.x) : (int)blockIdx.x;
        float pix = pos[3*i], piy = pos[3*i+1], piz = pos[3*i+2];

        int nt = (NN - i + 15) >> 4;     // uniform trip count across warp
        for (int it = 0; it < nt; it++) {
            int j   = i + jfix + (it << 4);
            bool ok = (j < NN);
            int jc  = ok ? j : (NN - 1);  // clamp for safe loads

            float dx = pix - pos[3*jc];
            float dy = piy - pos[3*jc+1];
            float dz = piz - pos[3*jc+2];
            float sq = dx*dx + dy*dy + dz*dz;
            float d  = (sq > 0.f) ? sqrtf(sq) : 0.f;
            float s3 = __expf(-0.25f * d);
            float s2 = s3 * s3;
            float s1 = s2 * s2;

            float v[8];
            #pragma unroll
            for (int k = 0; k < 8; k++)
                v[k] = silu_f(fmaf(s1, w0[k], fmaf(s2, w1[k], fmaf(s3, w2[k], wb[k]))));

            float p = ((v[0]+v[1])+(v[2]+v[3])) + ((v[4]+v[5])+(v[6]+v[7]));
            float q = fmaf(v[0],v[0], fmaf(v[1],v[1], fmaf(v[2],v[2], v[3]*v[3])))
                    + fmaf(v[4],v[4], fmaf(v[5],v[5], fmaf(v[6],v[6], v[7]*v[7])));
            #pragma unroll
            for (int off = 8; off; off >>= 1) {   // stays within 16-lane group
                p += __shfl_xor_sync(0xffffffffu, p, off);
                q += __shfl_xor_sync(0xffffffffu, q, off);
            }
            float mu   = p * (1.f/HH);
            float var  = fmaf(-mu, mu, q * (1.f/HH));
            float rstd = rsqrtf(var + LN_EPS);
            float c0   = -mu * rstd;

            __half2 oh[4];
            #pragma unroll
            for (int k = 0; k < 4; k++) {
                float oa = fmaf(fmaf(v[2*k],   rstd, c0), wg[2*k],   we[2*k]);
                float ob = fmaf(fmaf(v[2*k+1], rstd, c0), wg[2*k+1], we[2*k+1]);
                oh[k] = __floats2half2_rn(oa, ob);
            }
            uint4 pack;
            pack.x = *(unsigned*)&oh[0]; pack.y = *(unsigned*)&oh[1];
            pack.z = *(unsigned*)&oh[2]; pack.w = *(unsigned*)&oh[3];

            if (ok) {
                __stcs((uint4*)(g_ew + ((long long)i*NN + j)*HH + h0), pack);
                if (j != i)
                    __stcs((uint4*)(g_ew + ((long long)j*NN + i)*HH + h0), pack);
            }
        }
    }
}

// ---------------------------------------------------------------
// pre = x@Wi + msg_b, prj = x@Wj.  8 nodes/block, 128 threads (h).
__global__ void __launch_bounds__(128) k_preprj(
    const float* __restrict__ msgW, const float* __restrict__ msgb, int lvl)
{
    __shared__ float xs[8][HH];
    int h  = threadIdx.x;
    int n0 = blockIdx.x << 3;
    #pragma unroll
    for (int nn = 0; nn < 8; nn++) xs[nn][h] = g_x[(n0+nn)*HH + h];
    __syncthreads();

    const float* Wi = msgW + (size_t)lvl*2*HH*HH;
    const float* Wj = Wi + HH*HH;
    float ai[8], aj[8];
    #pragma unroll
    for (int nn = 0; nn < 8; nn++) { ai[nn] = 0.f; aj[nn] = 0.f; }

    for (int k = 0; k < HH; k++) {
        float wi = Wi[k*HH + h];
        float wj = Wj[k*HH + h];
        #pragma unroll
        for (int nn = 0; nn < 8; nn++) {
            ai[nn] = fmaf(xs[nn][k], wi, ai[nn]);
            aj[nn] = fmaf(xs[nn][k], wj, aj[nn]);
        }
    }
    float bb = msgb[lvl*HH + h];
    #pragma unroll
    for (int nn = 0; nn < 8; nn++) {
        g_pre[(n0+nn)*HH + h] = ai[nn] + bb;
        g_prj[(n0+nn)*HH + h] = aj[nn];
    }
}

// ---------------------------------------------------------------
// msum[i,h] = g[h]*sum_j (s-mu)*rstd*e  +  be[h]*sum_j e
// R9-proven form: contiguous full-matrix ew reads.
// 16 lanes per j (8 h each), 2 j per warp; 4-step group butterfly.
template<bool FIRST>
__global__ void __launch_bounds__(256) k_msum(
    const float* __restrict__ msgg, const float* __restrict__ msgbe, int lvl)
{
    __shared__ float red[16][HH];
    __shared__ float red2[16][HH];   // only used when FIRST
    int i    = blockIdx.x;
    int warp = threadIdx.x >> 5;
    int lane = threadIdx.x & 31;
    int grp  = lane >> 4;
    int l16  = lane & 15;
    int h0   = l16 << 3;

    float pre[8];
    *(float4*)(pre)     = *(const float4*)(g_pre + i*HH + h0);
    *(float4*)(pre + 4) = *(const float4*)(g_pre + i*HH + h0 + 4);

    float a[8] = {0,0,0,0,0,0,0,0};
    float z[8] = {0,0,0,0,0,0,0,0};

    const __half* ewbase = g_ew + (long long)i*NN*HH + h0;
    int jfix = (warp << 1) + grp;

    #pragma unroll 2
    for (int jj = 0; jj < NN/16; jj++) {
        int j = (jj << 4) + jfix;
        float4 pja = *(const float4*)(g_prj + j*HH + h0);
        float4 pjb = *(const float4*)(g_prj + j*HH + h0 + 4);
        uint4  epk = __ldcs((const uint4*)(ewbase + (long long)j*HH));

        float s[8];
        s[0] = silu_f(pre[0] + pja.x);
        s[1] = silu_f(pre[1] + pja.y);
        s[2] = silu_f(pre[2] + pja.z);
        s[3] = silu_f(pre[3] + pja.w);
        s[4] = silu_f(pre[4] + pjb.x);
        s[5] = silu_f(pre[5] + pjb.y);
        s[6] = silu_f(pre[6] + pjb.z);
        s[7] = silu_f(pre[7] + pjb.w);

        float p = ((s[0]+s[1])+(s[2]+s[3])) + ((s[4]+s[5])+(s[6]+s[7]));
        float q = fmaf(s[0],s[0], fmaf(s[1],s[1], fmaf(s[2],s[2], s[3]*s[3])))
                + fmaf(s[4],s[4], fmaf(s[5],s[5], fmaf(s[6],s[6], s[7]*s[7])));
        #pragma unroll
        for (int off = 8; off; off >>= 1) {
            p += __shfl_xor_sync(0xffffffffu, p, off);
            q += __shfl_xor_sync(0xffffffffu, q, off);
        }
        float mu   = p * (1.f/HH);
        float var  = fmaf(-mu, mu, q * (1.f/HH));
        float rstd = rsqrtf(var + LN_EPS);
        float c0   = -mu * rstd;

        unsigned u0 = epk.x, u1 = epk.y, u2 = epk.z, u3 = epk.w;
        float2 f0 = __half22float2(*(__half2*)&u0);
        float2 f1 = __half22float2(*(__half2*)&u1);
        float2 f2 = __half22float2(*(__half2*)&u2);
        float2 f3 = __half22float2(*(__half2*)&u3);
        float e[8] = { f0.x, f0.y, f1.x, f1.y, f2.x, f2.y, f3.x, f3.y };

        #pragma unroll
        for (int k = 0; k < 8; k++) {
            a[k] = fmaf(fmaf(s[k], rstd, c0), e[k], a[k]);
            if (FIRST) z[k] += e[k];
        }
    }

    int slot = (warp << 1) | grp;
    #pragma unroll
    for (int k = 0; k < 8; k++) red[slot][h0+k] = a[k];
    if (FIRST) {
        #pragma unroll
        for (int k = 0; k < 8; k++) red2[slot][h0+k] = z[k];
    }
    __syncthreads();
    if (threadIdx.x < HH) {
        int h = threadIdx.x;
        float S1 = 0.f, S0 = 0.f;
        #pragma unroll
        for (int w = 0; w < 16; w++) S1 += red[w][h];
        if (FIRST) {
            #pragma unroll
            for (int w = 0; w < 16; w++) S0 += red2[w][h];
            g_esum[i*HH + h] = S0;
        } else {
            S0 = g_esum[i*HH + h];
        }
        g_msum[i*HH + h] = fmaf(msgg[lvl*HH + h], S1, msgbe[lvl*HH + h] * S0);
    }
}

// ---------------------------------------------------------------
// x += LN(silu([x, msum] @ upd_W + upd_b)); accumulate level mean.
__global__ void __launch_bounds__(128) k_upd(
    const float* __restrict__ updW, const float* __restrict__ updb,
    const float* __restrict__ updg, const float* __restrict__ updbe, int lvl)
{
    __shared__ float us[2*HH];
    __shared__ float rp[4], rq[4];
    __shared__ float s_mu, s_rstd;
    int i = blockIdx.x;
    int h = threadIdx.x;
    int warp = h >> 5, lane = h & 31;

    us[h]      = g_x[i*HH + h];
    us[HH + h] = g_msum[i*HH + h];
    __syncthreads();

    const float* W = updW + (size_t)lvl*2*HH*HH;
    float acc = updb[lvl*HH + h];
    #pragma unroll 4
    for (int k = 0; k < 2*HH; k++) acc = fmaf(us[k], W[k*HH + h], acc);

    float s = silu_f(acc);

    float p = warp_sum(s);
    float q = warp_sum(s*s);
    if (lane == 0) { rp[warp] = p; rq[warp] = q; }
    __syncthreads();
    if (h == 0) {
        float P = rp[0]+rp[1]+rp[2]+rp[3];
        float Q = rq[0]+rq[1]+rq[2]+rq[3];
        float mu = P * (1.f/HH);
        s_mu = mu;
        s_rstd = rsqrtf(fmaf(-mu, mu, Q * (1.f/HH)) + LN_EPS);
    }
    __syncthreads();

    float m  = fmaf((s - s_mu) * s_rstd, updg[lvl*HH + h], updbe[lvl*HH + h]);
    float xn = us[h] + m;
    g_x[i*HH + h] = xn;
    atomicAdd(&g_lmean[lvl*HH + h], xn * (1.f/NN));
}

// ---------------------------------------------------------------
__global__ void __launch_bounds__(256) k_final(
    const float* __restrict__ fpW, const float* __restrict__ fpb,
    const float* __restrict__ fpg, const float* __restrict__ fpbe,
    float* __restrict__ out)
{
    __shared__ float cs[NLVL*HH];
    __shared__ float rp[8], rq[8];
    __shared__ float s_mu, s_rstd;
    int t = threadIdx.x;
    int warp = t >> 5, lane = t & 31;

    for (int k = t; k < NLVL*HH; k += 256) cs[k] = g_lmean[k];
    __syncthreads();

    float acc = fpb[t];
    #pragma unroll 4
    for (int k = 0; k < NLVL*HH; k++) acc = fmaf(cs[k], fpW[k*DD + t], acc);

    float p = warp_sum(acc);
    float q = warp_sum(acc*acc);
    if (lane == 0) { rp[warp] = p; rq[warp] = q; }
    __syncthreads();
    if (t == 0) {
        float P = 0.f, Q = 0.f;
        #pragma unroll
        for (int w = 0; w < 8; w++) { P += rp[w]; Q += rq[w]; }
        float mu = P * (1.f/DD);
        s_mu = mu;
        s_rstd = rsqrtf(fmaf(-mu, mu, Q * (1.f/DD)) + LN_EPS);
    }
    __syncthreads();

    out[t] = fmaf((acc - s_mu) * s_rstd, fpg[t], fpbe[t]);
}

// ---------------------------------------------------------------
extern "C" void kernel_launch(void* const* d_in, const int* in_sizes, int n_in,
                              void* d_out, int out_size) {
    const int*   an    = (const int*)  d_in[0];
    const float* pos   = (const float*)d_in[1];
    const float* emb   = (const float*)d_in[2];
    const float* deW   = (const float*)d_in[3];
    const float* deb   = (const float*)d_in[4];
    const float* deg   = (const float*)d_in[5];
    const float* debe  = (const float*)d_in[6];
    const float* msgW  = (const float*)d_in[7];
    const float* msgb  = (const float*)d_in[8];
    const float* msgg  = (const float*)d_in[9];
    const float* msgbe = (const float*)d_in[10];
    const float* updW  = (const float*)d_in[11];
    const float* updb  = (const float*)d_in[12];
    const float* updg  = (const float*)d_in[13];
    const float* updbe = (const float*)d_in[14];
    const float* fpW   = (const float*)d_in[15];
    const float* fpb   = (const float*)d_in[16];
    const float* fpg   = (const float*)d_in[17];
    const float* fpbe  = (const float*)d_in[18];
    float* out = (float*)d_out;

    k_init<<<512, 256>>>(an, emb);
    k_ew<<<512, 256>>>(pos, deW, deb, deg, debe);
    for (int lvl = 0; lvl < NLVL; lvl++) {
        k_preprj<<<128, 128>>>(msgW, msgb, lvl);
        if (lvl == 0) k_msum<true><<<1024, 256>>>(msgg, msgbe, lvl);
        else          k_msum<false><<<1024, 256>>>(msgg, msgbe, lvl);
        k_upd<<<1024, 128>>>(updW, updb, updg, updbe, lvl);
    }
    k_final<<<1, 256>>>(fpW, fpb, fpg, fpbe, out);
}